// round 8
// baseline (speedup 1.0000x reference)
#include <cuda_runtime.h>
#include <math.h>
#include <stdint.h>

// Problem constants (fixed by the dataset)
#define TT   4096          // tokens = B*S
#define HD   1024          // hidden
#define FD   4096          // ffn dim
#define NE   8             // experts
#define KSEL 2             // top-k
#define NSLOTS (TT * KSEL) // 8192 token-expert pairs

// ---------------- static scratch (no allocations allowed) ----------------
__device__ int   d_count[NE];
__device__ int   d_fill[NE];
__device__ int   d_offset[NE];
__device__ int   d_rows[NSLOTS];          // slot -> token
__device__ int   d_tope[TT * KSEL];       // token -> expert ids
__device__ int   d_slot[TT * KSEL];       // token -> slot ids
__device__ float d_wgt[TT * KSEL];        // token -> combine weights
__device__ float d_inter[(size_t)NSLOTS * FD];  // 128 MB
__device__ float d_y[(size_t)NSLOTS * HD];      // 32 MB

// ---------------- PTX helpers ----------------
__device__ __forceinline__ uint32_t smem_u32(const void* p) {
    uint32_t a;
    asm("{ .reg .u64 t; cvta.to.shared.u64 t, %1; cvt.u32.u64 %0, t; }" : "=r"(a) : "l"(p));
    return a;
}

#define CP16(s, g) \
    asm volatile("cp.async.cg.shared.global [%0], [%1], 16;" :: "r"(s), "l"(g) : "memory")
#define CPCOMMIT() asm volatile("cp.async.commit_group;" ::: "memory")
#define CPWAIT1()  asm volatile("cp.async.wait_group 1;" ::: "memory")
#define CPWAIT0()  asm volatile("cp.async.wait_group 0;" ::: "memory")

// round-to-nearest tf32 conversion (unbiased)
__device__ __forceinline__ uint32_t tf32r(float f) {
    uint32_t u;
    asm("cvt.rna.tf32.f32 %0, %1;" : "=r"(u) : "f"(f));
    return u;
}

// D += A*B, m16n8k8 tf32 (legacy HMMA path, assembles for plain sm_103)
__device__ __forceinline__ void mma8(float* c, uint32_t a0, uint32_t a1, uint32_t a2,
                                     uint32_t a3, uint32_t b0, uint32_t b1) {
    asm volatile(
        "mma.sync.aligned.m16n8k8.row.col.f32.tf32.tf32.f32 "
        "{%0,%1,%2,%3}, {%4,%5,%6,%7}, {%8,%9}, {%0,%1,%2,%3};"
        : "+f"(c[0]), "+f"(c[1]), "+f"(c[2]), "+f"(c[3])
        : "r"(a0), "r"(a1), "r"(a2), "r"(a3), "r"(b0), "r"(b1));
}

__device__ __forceinline__ float silu_mul(float v, float g) {
    return v / (1.f + __expf(-v)) * g;
}

// ---------------- routing kernels (correctness-proven) ----------------

__global__ void zero_counters_kernel() {
    int i = threadIdx.x;
    if (i < NE) { d_count[i] = 0; d_fill[i] = 0; }
}

__global__ void router_kernel(const float* __restrict__ x,
                              const float* __restrict__ gw,
                              float* __restrict__ logits_out) {
    int t    = blockIdx.x;
    int warp = threadIdx.x >> 5;
    int lane = threadIdx.x & 31;
    const float* xr = x + (size_t)t * HD;
    const float* gr = gw + (size_t)warp * HD;
    float s = 0.f;
    #pragma unroll 8
    for (int i = lane; i < HD; i += 32) s += xr[i] * gr[i];
    #pragma unroll
    for (int o = 16; o; o >>= 1) s += __shfl_xor_sync(0xffffffffu, s, o);
    __shared__ float sl[NE];
    if (lane == 0) sl[warp] = s;
    __syncthreads();
    if (threadIdx.x < NE) logits_out[(size_t)t * NE + threadIdx.x] = sl[threadIdx.x];
    if (threadIdx.x == 0) {
        float mx = sl[0];
        #pragma unroll
        for (int e = 1; e < NE; e++) mx = fmaxf(mx, sl[e]);
        float p[NE];
        #pragma unroll
        for (int e = 0; e < NE; e++) p[e] = expf(sl[e] - mx);
        int e0 = 0;
        #pragma unroll
        for (int e = 1; e < NE; e++) if (p[e] > p[e0]) e0 = e;
        int e1 = (e0 == 0) ? 1 : 0;
        #pragma unroll
        for (int e = 0; e < NE; e++) { if (e == e0) continue; if (p[e] > p[e1]) e1 = e; }
        float w0 = p[e0], w1 = p[e1];
        float ws = w0 + w1;
        w0 /= ws; w1 /= ws;
        d_tope[t * 2 + 0] = e0; d_tope[t * 2 + 1] = e1;
        d_wgt[t * 2 + 0] = w0;  d_wgt[t * 2 + 1] = w1;
        atomicAdd(&d_count[e0], 1);
        atomicAdd(&d_count[e1], 1);
    }
}

__global__ void offsets_kernel() {
    if (threadIdx.x == 0) {
        int acc = 0;
        #pragma unroll
        for (int e = 0; e < NE; e++) { d_offset[e] = acc; acc += d_count[e]; }
    }
}

__global__ void assign_kernel() {
    int t = blockIdx.x * blockDim.x + threadIdx.x;
    if (t >= TT) return;
    #pragma unroll
    for (int k = 0; k < KSEL; k++) {
        int e = d_tope[t * 2 + k];
        int pos = atomicAdd(&d_fill[e], 1);
        int s = d_offset[e] + pos;
        d_rows[s] = t;
        d_slot[t * 2 + k] = s;
    }
}

// ============= shared GEMM constants =============
#define ASTR 20                         // raw smem padded float stride (conflict-free)

// =================== GEMM1: tf32 mma.sync, fused SiLU·mul =================
// Block 128(M) x 64(N), BK=16, raw 3-stage cp.async + tf32 fragment-major
// ping-pong. 8 warps (4x2), warp tile 32x32, dual accumulators (w1 & w3).
#define G1_STG   20480                  // raw stage: A 128x16 + B1 64x16 + B3 64x16 (padded)
#define G1_B1O   10240
#define G1_B3O   15360
#define G1_FRAG  61440                  // frag base (after 3 raw stages)
#define G1_FSTG  16384                  // frag stage: A 8K + B1 4K + B3 4K
#define G1_TOK   (G1_FRAG + 2 * G1_FSTG)
#define G1_SMEM  (G1_TOK + 512)
#define G1_NKS   (HD / 16)

__device__ __forceinline__ void g1_load(uint32_t sbase, int st, int k0, int tid,
                                        const float* __restrict__ x,
                                        const int* __restrict__ tok,
                                        const float* __restrict__ W1,
                                        const float* __restrict__ W3) {
    uint32_t ab = sbase + (uint32_t)st * G1_STG;
    #pragma unroll
    for (int t = 0; t < 2; t++) {                 // A: 128 rows x 16 floats
        int c = tid + t * 256;
        int row = c >> 2, q = c & 3;
        CP16(ab + (uint32_t)(row * ASTR + q * 4) * 4,
             x + (size_t)tok[row] * HD + k0 + q * 4);
    }
    {
        int row = tid >> 2, q = tid & 3;          // B1/B3: 64 rows x 16 floats
        CP16(ab + G1_B1O + (uint32_t)(row * ASTR + q * 4) * 4,
             W1 + (size_t)row * HD + k0 + q * 4);
        CP16(ab + G1_B3O + (uint32_t)(row * ASTR + q * 4) * 4,
             W3 + (size_t)row * HD + k0 + q * 4);
    }
    CPCOMMIT();
}

// raw fp32 -> tf32 fragment-major. A: 512 groups of 4; B1/B3: 512 groups of 2.
__device__ __forceinline__ void g1_preconv(char* smem, int st, int fs, int tid) {
    const float* Ra = (const float*)(smem + (size_t)st * G1_STG);
    const float* R1 = (const float*)(smem + (size_t)st * G1_STG + G1_B1O);
    const float* R3 = (const float*)(smem + (size_t)st * G1_STG + G1_B3O);
    char* fbase = smem + G1_FRAG + (size_t)fs * G1_FSTG;
    uint4* fA  = (uint4*)fbase;
    uint2* f1  = (uint2*)(fbase + 8192);
    uint2* f3  = (uint2*)(fbase + 12288);
    #pragma unroll
    for (int i = 0; i < 2; i++) {                 // A groups
        int g = tid + i * 256;
        int m16 = g >> 6, k8 = (g >> 5) & 1, ln = g & 31;
        int r = m16 * 16 + (ln >> 2), c = k8 * 8 + (ln & 3);
        uint4 v;
        v.x = tf32r(Ra[r * ASTR + c]);
        v.y = tf32r(Ra[(r + 8) * ASTR + c]);
        v.z = tf32r(Ra[r * ASTR + c + 4]);
        v.w = tf32r(Ra[(r + 8) * ASTR + c + 4]);
        fA[g] = v;
    }
    #pragma unroll
    for (int i = 0; i < 2; i++) {                 // B1 + B3 groups
        int g = tid + i * 256;
        int n8 = g >> 6, k8 = (g >> 5) & 1, ln = g & 31;
        int r = n8 * 8 + (ln >> 2), c = k8 * 8 + (ln & 3);
        uint2 v;
        v.x = tf32r(R1[r * ASTR + c]);
        v.y = tf32r(R1[r * ASTR + c + 4]);
        f1[g] = v;
        v.x = tf32r(R3[r * ASTR + c]);
        v.y = tf32r(R3[r * ASTR + c + 4]);
        f3[g] = v;
    }
}

__global__ void __launch_bounds__(256, 2)
gemm1_mma(const float* __restrict__ x,
          const float* __restrict__ w1,
          const float* __restrict__ w3) {
    int e  = blockIdx.z;
    int nt = blockIdx.x;
    int m0 = blockIdx.y * 128;
    int cnt = d_count[e];
    if (m0 >= cnt) return;
    int base = d_offset[e];

    extern __shared__ char smem[];
    uint32_t sbase = smem_u32(smem);
    int* tok = (int*)(smem + G1_TOK);

    int tid = threadIdx.x;
    int wid = tid >> 5, lane = tid & 31;
    int wm = wid & 3, wn = wid >> 2;       // 4x2 warp grid
    int gid = lane >> 2, tig = lane & 3;

    if (tid < 128) {
        int m = m0 + tid;
        tok[tid] = d_rows[base + (m < cnt ? m : cnt - 1)];
    }
    __syncthreads();

    const float* W1 = w1 + (size_t)e * FD * HD + (size_t)(nt * 64) * HD;
    const float* W3 = w3 + (size_t)e * FD * HD + (size_t)(nt * 64) * HD;

    float acc1[2][4][4], acc3[2][4][4];
    #pragma unroll
    for (int i = 0; i < 2; i++)
        #pragma unroll
        for (int j = 0; j < 4; j++)
            #pragma unroll
            for (int k = 0; k < 4; k++) { acc1[i][j][k] = 0.f; acc3[i][j][k] = 0.f; }

    g1_load(sbase, 0,  0, tid, x, tok, W1, W3);
    g1_load(sbase, 1, 16, tid, x, tok, W1, W3);

    for (int ks = 0; ks < G1_NKS; ks++) {
        if (ks + 1 < G1_NKS) CPWAIT1(); else CPWAIT0();
        __syncthreads();
        if (ks + 2 < G1_NKS)
            g1_load(sbase, (ks + 2) % 3, (ks + 2) * 16, tid, x, tok, W1, W3);
        int fs = ks & 1;
        g1_preconv(smem, ks % 3, fs, tid);
        __syncthreads();

        const char* fbase = smem + G1_FRAG + (size_t)fs * G1_FSTG;
        #pragma unroll
        for (int k8 = 0; k8 < 2; k8++) {
            uint4 a[2];
            #pragma unroll
            for (int mf = 0; mf < 2; mf++)
                a[mf] = *(const uint4*)(fbase + (((wm * 2 + mf) * 2 + k8) * 32 + lane) * 16);
            uint2 b1[4], b3[4];
            #pragma unroll
            for (int nf = 0; nf < 4; nf++) {
                int n8 = wn * 4 + nf;
                b1[nf] = *(const uint2*)(fbase + 8192  + ((n8 * 2 + k8) * 32 + lane) * 8);
                b3[nf] = *(const uint2*)(fbase + 12288 + ((n8 * 2 + k8) * 32 + lane) * 8);
            }
            #pragma unroll
            for (int nf = 0; nf < 4; nf++)
                #pragma unroll
                for (int mf = 0; mf < 2; mf++) {
                    mma8(acc1[mf][nf], a[mf].x, a[mf].y, a[mf].z, a[mf].w, b1[nf].x, b1[nf].y);
                    mma8(acc3[mf][nf], a[mf].x, a[mf].y, a[mf].z, a[mf].w, b3[nf].x, b3[nf].y);
                }
        }
    }

    // fused SiLU(h1)*h3 epilogue -> d_inter
    #pragma unroll
    for (int mf = 0; mf < 2; mf++) {
        int r = wm * 32 + mf * 16 + gid;
        #pragma unroll
        for (int nf = 0; nf < 4; nf++) {
            int n = nt * 64 + wn * 32 + nf * 8 + tig * 2;
            if (m0 + r < cnt) {
                float2 o;
                o.x = silu_mul(acc1[mf][nf][0], acc3[mf][nf][0]);
                o.y = silu_mul(acc1[mf][nf][1], acc3[mf][nf][1]);
                *reinterpret_cast<float2*>(&d_inter[(size_t)(base + m0 + r) * FD + n]) = o;
            }
            if (m0 + r + 8 < cnt) {
                float2 o;
                o.x = silu_mul(acc1[mf][nf][2], acc3[mf][nf][2]);
                o.y = silu_mul(acc1[mf][nf][3], acc3[mf][nf][3]);
                *reinterpret_cast<float2*>(&d_inter[(size_t)(base + m0 + r + 8) * FD + n]) = o;
            }
        }
    }
}

// =================== GEMM2: tf32 mma.sync ================================
// Block 128(M) x 128(N), BK=16, raw 3-stage + frag ping-pong, 8 warps (2x4),
// warp tile 64x32.
#define G2_STG   20480                  // raw: A 128x16 + B 128x16 (padded)
#define G2_BO    10240
#define G2_FRAG  61440
#define G2_FSTG  16384                  // A 8K + B 8K
#define G2_SMEM  (G2_FRAG + 2 * G2_FSTG)
#define G2_NKS   (FD / 16)

__device__ __forceinline__ void g2_load(uint32_t sbase, int st, int k0, int tid,
                                        int base, int m0, int cnt,
                                        const float* __restrict__ W2) {
    uint32_t ab = sbase + (uint32_t)st * G2_STG;
    #pragma unroll
    for (int t = 0; t < 2; t++) {
        int c = tid + t * 256;
        int row = c >> 2, q = c & 3;
        int rg = m0 + row; if (rg >= cnt) rg = cnt - 1;
        CP16(ab + (uint32_t)(row * ASTR + q * 4) * 4,
             d_inter + (size_t)(base + rg) * FD + k0 + q * 4);
        CP16(ab + G2_BO + (uint32_t)(row * ASTR + q * 4) * 4,
             W2 + (size_t)row * FD + k0 + q * 4);
    }
    CPCOMMIT();
}

__device__ __forceinline__ void g2_preconv(char* smem, int st, int fs, int tid) {
    const float* Ra = (const float*)(smem + (size_t)st * G2_STG);
    const float* Rb = (const float*)(smem + (size_t)st * G2_STG + G2_BO);
    char* fbase = smem + G2_FRAG + (size_t)fs * G2_FSTG;
    uint4* fA = (uint4*)fbase;
    uint2* fB = (uint2*)(fbase + 8192);
    #pragma unroll
    for (int i = 0; i < 2; i++) {                 // A: 512 groups
        int g = tid + i * 256;
        int m16 = g >> 6, k8 = (g >> 5) & 1, ln = g & 31;
        int r = m16 * 16 + (ln >> 2), c = k8 * 8 + (ln & 3);
        uint4 v;
        v.x = tf32r(Ra[r * ASTR + c]);
        v.y = tf32r(Ra[(r + 8) * ASTR + c]);
        v.z = tf32r(Ra[r * ASTR + c + 4]);
        v.w = tf32r(Ra[(r + 8) * ASTR + c + 4]);
        fA[g] = v;
    }
    #pragma unroll
    for (int i = 0; i < 4; i++) {                 // B: 1024 groups
        int g = tid + i * 256;
        int n8 = g >> 6, k8 = (g >> 5) & 1, ln = g & 31;
        int r = n8 * 8 + (ln >> 2), c = k8 * 8 + (ln & 3);
        uint2 v;
        v.x = tf32r(Rb[r * ASTR + c]);
        v.y = tf32r(Rb[r * ASTR + c + 4]);
        fB[g] = v;
    }
}

__global__ void __launch_bounds__(256, 2)
gemm2_mma(const float* __restrict__ w2) {
    int e  = blockIdx.z;
    int nt = blockIdx.x;
    int m0 = blockIdx.y * 128;
    int cnt = d_count[e];
    if (m0 >= cnt) return;
    int base = d_offset[e];

    extern __shared__ char smem[];
    uint32_t sbase = smem_u32(smem);

    int tid = threadIdx.x;
    int wid = tid >> 5, lane = tid & 31;
    int wm = wid & 1, wn = wid >> 1;       // 2x4 warp grid
    int gid = lane >> 2, tig = lane & 3;

    const float* W2 = w2 + (size_t)e * HD * FD + (size_t)(nt * 128) * FD;

    float acc[4][4][4];
    #pragma unroll
    for (int i = 0; i < 4; i++)
        #pragma unroll
        for (int j = 0; j < 4; j++)
            #pragma unroll
            for (int k = 0; k < 4; k++) acc[i][j][k] = 0.f;

    g2_load(sbase, 0,  0, tid, base, m0, cnt, w2 ? W2 : W2);
    g2_load(sbase, 1, 16, tid, base, m0, cnt, W2);

    for (int ks = 0; ks < G2_NKS; ks++) {
        if (ks + 1 < G2_NKS) CPWAIT1(); else CPWAIT0();
        __syncthreads();
        if (ks + 2 < G2_NKS)
            g2_load(sbase, (ks + 2) % 3, (ks + 2) * 16, tid, base, m0, cnt, W2);
        int fs = ks & 1;
        g2_preconv(smem, ks % 3, fs, tid);
        __syncthreads();

        const char* fbase = smem + G2_FRAG + (size_t)fs * G2_FSTG;
        #pragma unroll
        for (int k8 = 0; k8 < 2; k8++) {
            uint4 a[4];
            #pragma unroll
            for (int mf = 0; mf < 4; mf++)
                a[mf] = *(const uint4*)(fbase + (((wm * 4 + mf) * 2 + k8) * 32 + lane) * 16);
            uint2 b[4];
            #pragma unroll
            for (int nf = 0; nf < 4; nf++) {
                int n8 = wn * 4 + nf;
                b[nf] = *(const uint2*)(fbase + 8192 + ((n8 * 2 + k8) * 32 + lane) * 8);
            }
            #pragma unroll
            for (int nf = 0; nf < 4; nf++)
                #pragma unroll
                for (int mf = 0; mf < 4; mf++)
                    mma8(acc[mf][nf], a[mf].x, a[mf].y, a[mf].z, a[mf].w, b[nf].x, b[nf].y);
        }
    }

    #pragma unroll
    for (int mf = 0; mf < 4; mf++) {
        int r = wm * 64 + mf * 16 + gid;
        #pragma unroll
        for (int nf = 0; nf < 4; nf++) {
            int n = nt * 128 + wn * 32 + nf * 8 + tig * 2;
            if (m0 + r < cnt) {
                float2 o = make_float2(acc[mf][nf][0], acc[mf][nf][1]);
                *reinterpret_cast<float2*>(&d_y[(size_t)(base + m0 + r) * HD + n]) = o;
            }
            if (m0 + r + 8 < cnt) {
                float2 o = make_float2(acc[mf][nf][2], acc[mf][nf][3]);
                *reinterpret_cast<float2*>(&d_y[(size_t)(base + m0 + r + 8) * HD + n]) = o;
            }
        }
    }
}

// ---------------- combine ----------------
__global__ void combine_kernel(float* __restrict__ out) {
    int idx = blockIdx.x * blockDim.x + threadIdx.x;
    if (idx >= TT * (HD / 4)) return;
    int t  = idx / (HD / 4);
    int h4 = (idx % (HD / 4)) * 4;
    int s0 = d_slot[t * 2 + 0], s1 = d_slot[t * 2 + 1];
    float w0 = d_wgt[t * 2 + 0], w1 = d_wgt[t * 2 + 1];
    float4 y0 = *reinterpret_cast<const float4*>(&d_y[(size_t)s0 * HD + h4]);
    float4 y1 = *reinterpret_cast<const float4*>(&d_y[(size_t)s1 * HD + h4]);
    float4 o;
    o.x = w0 * y0.x + w1 * y1.x;
    o.y = w0 * y0.y + w1 * y1.y;
    o.z = w0 * y0.z + w1 * y1.z;
    o.w = w0 * y0.w + w1 * y1.w;
    *reinterpret_cast<float4*>(&out[(size_t)t * HD + h4]) = o;
}

// ---------------- launch ----------------
extern "C" void kernel_launch(void* const* d_in, const int* in_sizes, int n_in,
                              void* d_out, int out_size) {
    const float* x   = (const float*)d_in[0];  // [T, H]
    const float* gw  = (const float*)d_in[1];  // [E, H]
    const float* w1  = (const float*)d_in[2];  // [E, F, H]
    const float* w2  = (const float*)d_in[3];  // [E, H, F]
    const float* w3  = (const float*)d_in[4];  // [E, F, H]
    float* out       = (float*)d_out;          // [T*H] then logits [T*E]
    float* logits    = out + (size_t)TT * HD;

    cudaFuncSetAttribute(gemm1_mma, cudaFuncAttributeMaxDynamicSharedMemorySize, G1_SMEM);
    cudaFuncSetAttribute(gemm2_mma, cudaFuncAttributeMaxDynamicSharedMemorySize, G2_SMEM);

    zero_counters_kernel<<<1, 32>>>();
    router_kernel<<<TT, 256>>>(x, gw, logits);
    offsets_kernel<<<1, 32>>>();
    assign_kernel<<<(TT + 255) / 256, 256>>>();

    dim3 g1(FD / 64, TT / 128, NE);    // (64, 32, 8), dead tiles early-exit
    gemm1_mma<<<g1, 256, G1_SMEM>>>(x, w1, w3);

    dim3 g2(HD / 128, TT / 128, NE);   // (8, 32, 8)
    gemm2_mma<<<g2, 256, G2_SMEM>>>(w2);

    combine_kernel<<<(TT * (HD / 4) + 255) / 256, 256>>>(out);
}

// round 9
// speedup vs baseline: 1.1118x; 1.1118x over previous
#include <cuda_runtime.h>
#include <math.h>
#include <stdint.h>

// Problem constants (fixed by the dataset)
#define TT   4096          // tokens = B*S
#define HD   1024          // hidden
#define FD   4096          // ffn dim
#define NE   8             // experts
#define KSEL 2             // top-k
#define NSLOTS (TT * KSEL) // 8192 token-expert pairs

// ---------------- static scratch (no allocations allowed) ----------------
__device__ int   d_count[NE];
__device__ int   d_fill[NE];
__device__ int   d_offset[NE];
__device__ int   d_rows[NSLOTS];          // slot -> token
__device__ int   d_tope[TT * KSEL];       // token -> expert ids
__device__ int   d_slot[TT * KSEL];       // token -> slot ids
__device__ float d_wgt[TT * KSEL];        // token -> combine weights
__device__ float d_inter[(size_t)NSLOTS * FD];  // 128 MB (stored pre-rounded to tf32)
__device__ float d_y[(size_t)NSLOTS * HD];      // 32 MB
// pre-rounded tf32 copies (rounding once in gmem removes all cvt from GEMM inner loops)
__device__ float d_xr [(size_t)TT * HD];        // 16 MB
__device__ float d_w1r[(size_t)NE * FD * HD];   // 128 MB
__device__ float d_w3r[(size_t)NE * FD * HD];   // 128 MB
__device__ float d_w2r[(size_t)NE * HD * FD];   // 128 MB

// ---------------- PTX helpers ----------------
__device__ __forceinline__ uint32_t smem_u32(const void* p) {
    uint32_t a;
    asm("{ .reg .u64 t; cvta.to.shared.u64 t, %1; cvt.u32.u64 %0, t; }" : "=r"(a) : "l"(p));
    return a;
}

#define CP16(s, g) \
    asm volatile("cp.async.cg.shared.global [%0], [%1], 16;" :: "r"(s), "l"(g) : "memory")
#define CPCOMMIT() asm volatile("cp.async.commit_group;" ::: "memory")
#define CPWAIT1()  asm volatile("cp.async.wait_group 1;" ::: "memory")
#define CPWAIT0()  asm volatile("cp.async.wait_group 0;" ::: "memory")

// round-to-nearest tf32 conversion (unbiased); idempotent
__device__ __forceinline__ uint32_t tf32r(float f) {
    uint32_t u;
    asm("cvt.rna.tf32.f32 %0, %1;" : "=r"(u) : "f"(f));
    return u;
}

// D += A*B, m16n8k8 tf32 (legacy HMMA path, assembles for plain sm_103)
__device__ __forceinline__ void mma8(float* c, uint32_t a0, uint32_t a1, uint32_t a2,
                                     uint32_t a3, uint32_t b0, uint32_t b1) {
    asm volatile(
        "mma.sync.aligned.m16n8k8.row.col.f32.tf32.tf32.f32 "
        "{%0,%1,%2,%3}, {%4,%5,%6,%7}, {%8,%9}, {%0,%1,%2,%3};"
        : "+f"(c[0]), "+f"(c[1]), "+f"(c[2]), "+f"(c[3])
        : "r"(a0), "r"(a1), "r"(a2), "r"(a3), "r"(b0), "r"(b1));
}

__device__ __forceinline__ float silu_mul(float v, float g) {
    return v / (1.f + __expf(-v)) * g;
}

// ---------------- pre-round pass: fp32 -> tf32-rounded fp32 copies ----------
__global__ void round_kernel(const float* __restrict__ src, float* __restrict__ dst,
                             int n4) {
    int i = blockIdx.x * blockDim.x + threadIdx.x;
    if (i >= n4) return;
    float4 v = reinterpret_cast<const float4*>(src)[i];
    uint4 o;
    o.x = tf32r(v.x); o.y = tf32r(v.y); o.z = tf32r(v.z); o.w = tf32r(v.w);
    reinterpret_cast<uint4*>(dst)[i] = o;
}

// ---------------- routing kernels (correctness-proven) ----------------

__global__ void zero_counters_kernel() {
    int i = threadIdx.x;
    if (i < NE) { d_count[i] = 0; d_fill[i] = 0; }
}

__global__ void router_kernel(const float* __restrict__ x,
                              const float* __restrict__ gw,
                              float* __restrict__ logits_out) {
    int t    = blockIdx.x;
    int warp = threadIdx.x >> 5;
    int lane = threadIdx.x & 31;
    const float* xr = x + (size_t)t * HD;
    const float* gr = gw + (size_t)warp * HD;
    float s = 0.f;
    #pragma unroll 8
    for (int i = lane; i < HD; i += 32) s += xr[i] * gr[i];
    #pragma unroll
    for (int o = 16; o; o >>= 1) s += __shfl_xor_sync(0xffffffffu, s, o);
    __shared__ float sl[NE];
    if (lane == 0) sl[warp] = s;
    __syncthreads();
    if (threadIdx.x < NE) logits_out[(size_t)t * NE + threadIdx.x] = sl[threadIdx.x];
    if (threadIdx.x == 0) {
        float mx = sl[0];
        #pragma unroll
        for (int e = 1; e < NE; e++) mx = fmaxf(mx, sl[e]);
        float p[NE];
        #pragma unroll
        for (int e = 0; e < NE; e++) p[e] = expf(sl[e] - mx);
        int e0 = 0;
        #pragma unroll
        for (int e = 1; e < NE; e++) if (p[e] > p[e0]) e0 = e;
        int e1 = (e0 == 0) ? 1 : 0;
        #pragma unroll
        for (int e = 0; e < NE; e++) { if (e == e0) continue; if (p[e] > p[e1]) e1 = e; }
        float w0 = p[e0], w1 = p[e1];
        float ws = w0 + w1;
        w0 /= ws; w1 /= ws;
        d_tope[t * 2 + 0] = e0; d_tope[t * 2 + 1] = e1;
        d_wgt[t * 2 + 0] = w0;  d_wgt[t * 2 + 1] = w1;
        atomicAdd(&d_count[e0], 1);
        atomicAdd(&d_count[e1], 1);
    }
}

__global__ void offsets_kernel() {
    if (threadIdx.x == 0) {
        int acc = 0;
        #pragma unroll
        for (int e = 0; e < NE; e++) { d_offset[e] = acc; acc += d_count[e]; }
    }
}

__global__ void assign_kernel() {
    int t = blockIdx.x * blockDim.x + threadIdx.x;
    if (t >= TT) return;
    #pragma unroll
    for (int k = 0; k < KSEL; k++) {
        int e = d_tope[t * 2 + k];
        int pos = atomicAdd(&d_fill[e], 1);
        int s = d_offset[e] + pos;
        d_rows[s] = t;
        d_slot[t * 2 + k] = s;
    }
}

// ============= shared GEMM constants =============
#define ASTR 20                         // padded float stride (conflict-free)

// =================== GEMM1: tf32 mma.sync, fused SiLU·mul =================
// Block tile 128(M slots) x 64(N ffn), BK=16, 3-stage cp.async, 256 thr.
// 8 warps in 4x2 grid, warp tile 32x32, dual accumulators (w1 & w3).
// All operands pre-rounded in gmem -> NO cvt in the inner loop.
#define G1_STG 20480                    // 128*20*4 + 2*64*20*4
#define G1_B1O 10240
#define G1_B3O 15360
#define G1_SMEM (3 * G1_STG + 512)
#define G1_NKS  (HD / 16)

__device__ __forceinline__ void g1_load(uint32_t sbase, int st, int k0, int tid,
                                        const int* __restrict__ tok,
                                        const float* __restrict__ W1,
                                        const float* __restrict__ W3) {
    uint32_t ab = sbase + (uint32_t)st * G1_STG;
    #pragma unroll
    for (int t = 0; t < 2; t++) {                 // A: 128 rows x 16 floats
        int c = tid + t * 256;
        int row = c >> 2, q = c & 3;
        CP16(ab + (uint32_t)(row * ASTR + q * 4) * 4,
             d_xr + (size_t)tok[row] * HD + k0 + q * 4);
    }
    {
        int row = tid >> 2, q = tid & 3;          // B1/B3: 64 rows x 16 floats each
        CP16(ab + G1_B1O + (uint32_t)(row * ASTR + q * 4) * 4,
             W1 + (size_t)row * HD + k0 + q * 4);
        CP16(ab + G1_B3O + (uint32_t)(row * ASTR + q * 4) * 4,
             W3 + (size_t)row * HD + k0 + q * 4);
    }
    CPCOMMIT();
}

__global__ void __launch_bounds__(256, 2)
gemm1_mma() {
    int e  = blockIdx.z;
    int nt = blockIdx.x;
    int m0 = blockIdx.y * 128;
    int cnt = d_count[e];
    if (m0 >= cnt) return;
    int base = d_offset[e];

    extern __shared__ char smem[];
    uint32_t sbase = smem_u32(smem);
    int* tok = (int*)(smem + 3 * G1_STG);

    int tid = threadIdx.x;
    int wid = tid >> 5, lane = tid & 31;
    int wm = wid & 3, wn = wid >> 2;       // 4x2 warp grid
    int gid = lane >> 2, tig = lane & 3;

    if (tid < 128) {
        int m = m0 + tid;
        tok[tid] = d_rows[base + (m < cnt ? m : cnt - 1)];
    }
    __syncthreads();

    const float* W1 = d_w1r + (size_t)e * FD * HD + (size_t)(nt * 64) * HD;
    const float* W3 = d_w3r + (size_t)e * FD * HD + (size_t)(nt * 64) * HD;

    float acc1[2][4][4], acc3[2][4][4];
    #pragma unroll
    for (int i = 0; i < 2; i++)
        #pragma unroll
        for (int j = 0; j < 4; j++)
            #pragma unroll
            for (int k = 0; k < 4; k++) { acc1[i][j][k] = 0.f; acc3[i][j][k] = 0.f; }

    g1_load(sbase, 0,  0, tid, tok, W1, W3);
    g1_load(sbase, 1, 16, tid, tok, W1, W3);

    for (int ks = 0; ks < G1_NKS; ks++) {
        if (ks + 1 < G1_NKS) CPWAIT1(); else CPWAIT0();
        __syncthreads();
        if (ks + 2 < G1_NKS)
            g1_load(sbase, (ks + 2) % 3, (ks + 2) * 16, tid, tok, W1, W3);

        int st = ks % 3;
        const uint32_t* fA  = (const uint32_t*)(smem + (size_t)st * G1_STG);
        const uint32_t* fB1 = (const uint32_t*)(smem + (size_t)st * G1_STG + G1_B1O);
        const uint32_t* fB3 = (const uint32_t*)(smem + (size_t)st * G1_STG + G1_B3O);

        #pragma unroll
        for (int k8 = 0; k8 < 2; k8++) {
            int kk = k8 * 8;
            uint32_t a[2][4];
            #pragma unroll
            for (int mf = 0; mf < 2; mf++) {
                int r = wm * 32 + mf * 16 + gid;
                a[mf][0] = fA[r * ASTR + kk + tig];
                a[mf][1] = fA[(r + 8) * ASTR + kk + tig];
                a[mf][2] = fA[r * ASTR + kk + tig + 4];
                a[mf][3] = fA[(r + 8) * ASTR + kk + tig + 4];
            }
            #pragma unroll
            for (int nf = 0; nf < 4; nf++) {
                int n = wn * 32 + nf * 8 + gid;
                uint32_t b10 = fB1[n * ASTR + kk + tig];
                uint32_t b11 = fB1[n * ASTR + kk + tig + 4];
                uint32_t b30 = fB3[n * ASTR + kk + tig];
                uint32_t b31 = fB3[n * ASTR + kk + tig + 4];
                #pragma unroll
                for (int mf = 0; mf < 2; mf++) {
                    mma8(acc1[mf][nf], a[mf][0], a[mf][1], a[mf][2], a[mf][3], b10, b11);
                    mma8(acc3[mf][nf], a[mf][0], a[mf][1], a[mf][2], a[mf][3], b30, b31);
                }
            }
        }
        __syncthreads();
    }

    // fused SiLU(h1)*h3 epilogue -> d_inter, stored PRE-ROUNDED to tf32
    // (bit-identical to GEMM2 cvt'ing at read, but removes GEMM2's A-cvt)
    #pragma unroll
    for (int mf = 0; mf < 2; mf++) {
        int r = wm * 32 + mf * 16 + gid;
        #pragma unroll
        for (int nf = 0; nf < 4; nf++) {
            int n = nt * 64 + wn * 32 + nf * 8 + tig * 2;
            if (m0 + r < cnt) {
                uint2 o;
                o.x = tf32r(silu_mul(acc1[mf][nf][0], acc3[mf][nf][0]));
                o.y = tf32r(silu_mul(acc1[mf][nf][1], acc3[mf][nf][1]));
                *reinterpret_cast<uint2*>(&d_inter[(size_t)(base + m0 + r) * FD + n]) = o;
            }
            if (m0 + r + 8 < cnt) {
                uint2 o;
                o.x = tf32r(silu_mul(acc1[mf][nf][2], acc3[mf][nf][2]));
                o.y = tf32r(silu_mul(acc1[mf][nf][3], acc3[mf][nf][3]));
                *reinterpret_cast<uint2*>(&d_inter[(size_t)(base + m0 + r + 8) * FD + n]) = o;
            }
        }
    }
}

// =================== GEMM2: tf32 mma.sync ================================
// Block tile 128(M) x 128(N hidden), BK=16, 3-stage, 256 thr.
// 8 warps in 2x4 grid, warp tile 64x32. No cvt (operands pre-rounded).
#define G2_STG 20480                    // 2 * 128*20*4
#define G2_BO  10240
#define G2_SMEM (3 * G2_STG)
#define G2_NKS  (FD / 16)

__device__ __forceinline__ void g2_load(uint32_t sbase, int st, int k0, int tid,
                                        int base, int m0, int cnt,
                                        const float* __restrict__ W2) {
    uint32_t ab = sbase + (uint32_t)st * G2_STG;
    #pragma unroll
    for (int t = 0; t < 2; t++) {
        int c = tid + t * 256;
        int row = c >> 2, q = c & 3;
        int rg = m0 + row; if (rg >= cnt) rg = cnt - 1;
        CP16(ab + (uint32_t)(row * ASTR + q * 4) * 4,
             d_inter + (size_t)(base + rg) * FD + k0 + q * 4);
        CP16(ab + G2_BO + (uint32_t)(row * ASTR + q * 4) * 4,
             W2 + (size_t)row * FD + k0 + q * 4);
    }
    CPCOMMIT();
}

__global__ void __launch_bounds__(256, 2)
gemm2_mma() {
    int e  = blockIdx.z;
    int nt = blockIdx.x;
    int m0 = blockIdx.y * 128;
    int cnt = d_count[e];
    if (m0 >= cnt) return;
    int base = d_offset[e];

    extern __shared__ char smem[];
    uint32_t sbase = smem_u32(smem);

    int tid = threadIdx.x;
    int wid = tid >> 5, lane = tid & 31;
    int wm = wid & 1, wn = wid >> 1;       // 2x4 warp grid
    int gid = lane >> 2, tig = lane & 3;

    const float* W2 = d_w2r + (size_t)e * HD * FD + (size_t)(nt * 128) * FD;

    float acc[4][4][4];
    #pragma unroll
    for (int i = 0; i < 4; i++)
        #pragma unroll
        for (int j = 0; j < 4; j++)
            #pragma unroll
            for (int k = 0; k < 4; k++) acc[i][j][k] = 0.f;

    g2_load(sbase, 0,  0, tid, base, m0, cnt, W2);
    g2_load(sbase, 1, 16, tid, base, m0, cnt, W2);

    for (int ks = 0; ks < G2_NKS; ks++) {
        if (ks + 1 < G2_NKS) CPWAIT1(); else CPWAIT0();
        __syncthreads();
        if (ks + 2 < G2_NKS)
            g2_load(sbase, (ks + 2) % 3, (ks + 2) * 16, tid, base, m0, cnt, W2);

        int st = ks % 3;
        const uint32_t* fA = (const uint32_t*)(smem + (size_t)st * G2_STG);
        const uint32_t* fB = (const uint32_t*)(smem + (size_t)st * G2_STG + G2_BO);

        #pragma unroll
        for (int k8 = 0; k8 < 2; k8++) {
            int kk = k8 * 8;
            uint32_t a[4][4];
            #pragma unroll
            for (int mf = 0; mf < 4; mf++) {
                int r = wm * 64 + mf * 16 + gid;
                a[mf][0] = fA[r * ASTR + kk + tig];
                a[mf][1] = fA[(r + 8) * ASTR + kk + tig];
                a[mf][2] = fA[r * ASTR + kk + tig + 4];
                a[mf][3] = fA[(r + 8) * ASTR + kk + tig + 4];
            }
            #pragma unroll
            for (int nf = 0; nf < 4; nf++) {
                int n = wn * 32 + nf * 8 + gid;
                uint32_t b0 = fB[n * ASTR + kk + tig];
                uint32_t b1 = fB[n * ASTR + kk + tig + 4];
                #pragma unroll
                for (int mf = 0; mf < 4; mf++)
                    mma8(acc[mf][nf], a[mf][0], a[mf][1], a[mf][2], a[mf][3], b0, b1);
            }
        }
        __syncthreads();
    }

    #pragma unroll
    for (int mf = 0; mf < 4; mf++) {
        int r = wm * 64 + mf * 16 + gid;
        #pragma unroll
        for (int nf = 0; nf < 4; nf++) {
            int n = nt * 128 + wn * 32 + nf * 8 + tig * 2;
            if (m0 + r < cnt) {
                float2 o = make_float2(acc[mf][nf][0], acc[mf][nf][1]);
                *reinterpret_cast<float2*>(&d_y[(size_t)(base + m0 + r) * HD + n]) = o;
            }
            if (m0 + r + 8 < cnt) {
                float2 o = make_float2(acc[mf][nf][2], acc[mf][nf][3]);
                *reinterpret_cast<float2*>(&d_y[(size_t)(base + m0 + r + 8) * HD + n]) = o;
            }
        }
    }
}

// ---------------- combine ----------------
__global__ void combine_kernel(float* __restrict__ out) {
    int idx = blockIdx.x * blockDim.x + threadIdx.x;
    if (idx >= TT * (HD / 4)) return;
    int t  = idx / (HD / 4);
    int h4 = (idx % (HD / 4)) * 4;
    int s0 = d_slot[t * 2 + 0], s1 = d_slot[t * 2 + 1];
    float w0 = d_wgt[t * 2 + 0], w1 = d_wgt[t * 2 + 1];
    float4 y0 = *reinterpret_cast<const float4*>(&d_y[(size_t)s0 * HD + h4]);
    float4 y1 = *reinterpret_cast<const float4*>(&d_y[(size_t)s1 * HD + h4]);
    float4 o;
    o.x = w0 * y0.x + w1 * y1.x;
    o.y = w0 * y0.y + w1 * y1.y;
    o.z = w0 * y0.z + w1 * y1.z;
    o.w = w0 * y0.w + w1 * y1.w;
    *reinterpret_cast<float4*>(&out[(size_t)t * HD + h4]) = o;
}

// ---------------- launch ----------------
extern "C" void kernel_launch(void* const* d_in, const int* in_sizes, int n_in,
                              void* d_out, int out_size) {
    const float* x   = (const float*)d_in[0];  // [T, H]
    const float* gw  = (const float*)d_in[1];  // [E, H]
    const float* w1  = (const float*)d_in[2];  // [E, F, H]
    const float* w2  = (const float*)d_in[3];  // [E, H, F]
    const float* w3  = (const float*)d_in[4];  // [E, F, H]
    float* out       = (float*)d_out;          // [T*H] then logits [T*E]
    float* logits    = out + (size_t)TT * HD;

    cudaFuncSetAttribute(gemm1_mma, cudaFuncAttributeMaxDynamicSharedMemorySize, G1_SMEM);
    cudaFuncSetAttribute(gemm2_mma, cudaFuncAttributeMaxDynamicSharedMemorySize, G2_SMEM);

    float* xr;  cudaGetSymbolAddress((void**)&xr,  d_xr);
    float* w1r; cudaGetSymbolAddress((void**)&w1r, d_w1r);
    float* w3r; cudaGetSymbolAddress((void**)&w3r, d_w3r);
    float* w2r; cudaGetSymbolAddress((void**)&w2r, d_w2r);

    // pre-round inputs to tf32 in gmem (removes every cvt from GEMM hot loops)
    const int NW4 = (NE * FD * HD) / 4;                 // 8.4M float4 per weight tensor
    round_kernel<<<(NW4 + 255) / 256, 256>>>(w1, w1r, NW4);
    round_kernel<<<(NW4 + 255) / 256, 256>>>(w3, w3r, NW4);
    round_kernel<<<(NW4 + 255) / 256, 256>>>(w2, w2r, NW4);
    const int NX4 = (TT * HD) / 4;
    round_kernel<<<(NX4 + 255) / 256, 256>>>(x, xr, NX4);

    zero_counters_kernel<<<1, 32>>>();
    router_kernel<<<TT, 256>>>(x, gw, logits);          // router uses EXACT fp32 inputs
    offsets_kernel<<<1, 32>>>();
    assign_kernel<<<(TT + 255) / 256, 256>>>();

    dim3 g1(FD / 64, TT / 128, NE);    // (64, 32, 8), dead tiles early-exit
    gemm1_mma<<<g1, 256, G1_SMEM>>>();

    dim3 g2(HD / 128, TT / 128, NE);   // (8, 32, 8)
    gemm2_mma<<<g2, 256, G2_SMEM>>>();

    combine_kernel<<<(TT * (HD / 4) + 255) / 256, 256>>>(out);
}

// round 10
// speedup vs baseline: 1.8409x; 1.6558x over previous
#include <cuda_runtime.h>
#include <cuda_fp16.h>
#include <math.h>
#include <stdint.h>

// Problem constants (fixed by the dataset)
#define TT   4096
#define HD   1024
#define FD   4096
#define NE   8
#define KSEL 2
#define NSLOTS (TT * KSEL)
#define NSP   9216            // padded slots: 8192 + 8*128 headroom
#define SBLK  (NSP / 16)      // 576 slot blocks of 16
#define KB1   (HD / 16)       // 64  k16-blocks for GEMM1
#define NB1   (FD / 8)        // 512 n8-blocks  for GEMM1 weights
#define KB2   (FD / 16)       // 256 k16-blocks for GEMM2
#define NB2   (HD / 8)        // 128 n8-blocks  for GEMM2 weights

// ---------------- static scratch ----------------
__device__ int   d_count[NE];
__device__ int   d_fill[NE];
__device__ int   d_offset[NE];            // padded (multiple of 128) cumsum
__device__ int   d_rows[NSP];             // slot -> token (0 for padding)
__device__ int   d_tope[TT * KSEL];
__device__ int   d_slot[TT * KSEL];
__device__ float d_wgt[TT * KSEL];
__device__ float d_y[(size_t)NSP * HD];                       // 37.7 MB fp32
// fragment-major fp16 tensors (each uint4/uint2 = one lane's mma fragment)
__device__ __align__(16) uint4 d_xh [(size_t)SBLK * KB1 * 32];        // A frags G1
__device__ __align__(16) uint2 d_w1h[(size_t)NE * NB1 * KB1 * 32];    // B frags G1
__device__ __align__(16) uint2 d_w3h[(size_t)NE * NB1 * KB1 * 32];
__device__ __align__(16) uint4 d_ih [(size_t)SBLK * KB2 * 32];        // A frags G2 (inter)
__device__ __align__(16) uint2 d_w2h[(size_t)NE * NB2 * KB2 * 32];    // B frags G2

// ---------------- PTX helpers ----------------
__device__ __forceinline__ uint32_t smem_u32(const void* p) {
    uint32_t a;
    asm("{ .reg .u64 t; cvta.to.shared.u64 t, %1; cvt.u32.u64 %0, t; }" : "=r"(a) : "l"(p));
    return a;
}
#define CP16(s, g) \
    asm volatile("cp.async.cg.shared.global [%0], [%1], 16;" :: "r"(s), "l"(g) : "memory")
#define CPCOMMIT() asm volatile("cp.async.commit_group;" ::: "memory")
#define CPWAIT1()  asm volatile("cp.async.wait_group 1;" ::: "memory")
#define CPWAIT0()  asm volatile("cp.async.wait_group 0;" ::: "memory")

__device__ __forceinline__ uint32_t h2u(float a, float b) {
    __half2 h = __floats2half2_rn(a, b);
    return *reinterpret_cast<uint32_t*>(&h);
}

// D += A*B, m16n8k16 fp16 in / fp32 accum
__device__ __forceinline__ void mma16(float* c, uint32_t a0, uint32_t a1, uint32_t a2,
                                      uint32_t a3, uint32_t b0, uint32_t b1) {
    asm volatile(
        "mma.sync.aligned.m16n8k16.row.col.f32.f16.f16.f32 "
        "{%0,%1,%2,%3}, {%4,%5,%6,%7}, {%8,%9}, {%0,%1,%2,%3};"
        : "+f"(c[0]), "+f"(c[1]), "+f"(c[2]), "+f"(c[3])
        : "r"(a0), "r"(a1), "r"(a2), "r"(a3), "r"(b0), "r"(b1));
}

__device__ __forceinline__ float silu_mul(float v, float g) {
    return v / (1.f + __expf(-v)) * g;
}

// ---------------- prepass: fp32 weights -> fp16 fragment-major ----------------
// B-fragment of m16n8k16 for lane l (gid=l>>2, tig=l&3), n8-block nb, k16-block kb:
//   b0 = {W[nb*8+gid][kb*16+2tig], [+1]},  b1 = {... +8, +9}
__global__ void conv_w_kernel(const float* __restrict__ W, uint2* __restrict__ out,
                              int NBLK, int KBLK) {
    int idx  = blockIdx.x * 256 + threadIdx.x;       // over NE*NBLK*KBLK*32
    int lane = idx & 31;
    int rest = idx >> 5;
    int kb   = rest % KBLK;
    int nb   = (rest / KBLK) % NBLK;
    int e    = rest / (KBLK * NBLK);
    if (e >= NE) return;
    int gid = lane >> 2, tig = lane & 3;
    int K   = KBLK * 16;
    size_t row = (size_t)(e * NBLK + nb) * 8 + gid;
    int c   = kb * 16 + 2 * tig;
    float2 v0 = *reinterpret_cast<const float2*>(W + row * K + c);
    float2 v1 = *reinterpret_cast<const float2*>(W + row * K + c + 8);
    uint2 o;
    o.x = h2u(v0.x, v0.y);
    o.y = h2u(v1.x, v1.y);
    out[(size_t)idx] = o;
}

// ---------------- routing kernels ----------------
__global__ void zero_counters_kernel() {
    int i = threadIdx.x;
    if (i < NE) { d_count[i] = 0; d_fill[i] = 0; }
}

__global__ void zero_rows_kernel() {
    int i = blockIdx.x * blockDim.x + threadIdx.x;
    if (i < NSP) d_rows[i] = 0;
}

__global__ void router_kernel(const float* __restrict__ x,
                              const float* __restrict__ gw,
                              float* __restrict__ logits_out) {
    int t    = blockIdx.x;
    int warp = threadIdx.x >> 5;
    int lane = threadIdx.x & 31;
    const float* xr = x + (size_t)t * HD;
    const float* gr = gw + (size_t)warp * HD;
    float s = 0.f;
    #pragma unroll 8
    for (int i = lane; i < HD; i += 32) s += xr[i] * gr[i];
    #pragma unroll
    for (int o = 16; o; o >>= 1) s += __shfl_xor_sync(0xffffffffu, s, o);
    __shared__ float sl[NE];
    if (lane == 0) sl[warp] = s;
    __syncthreads();
    if (threadIdx.x < NE) logits_out[(size_t)t * NE + threadIdx.x] = sl[threadIdx.x];
    if (threadIdx.x == 0) {
        float mx = sl[0];
        #pragma unroll
        for (int e = 1; e < NE; e++) mx = fmaxf(mx, sl[e]);
        float p[NE];
        #pragma unroll
        for (int e = 0; e < NE; e++) p[e] = expf(sl[e] - mx);
        int e0 = 0;
        #pragma unroll
        for (int e = 1; e < NE; e++) if (p[e] > p[e0]) e0 = e;
        int e1 = (e0 == 0) ? 1 : 0;
        #pragma unroll
        for (int e = 0; e < NE; e++) { if (e == e0) continue; if (p[e] > p[e1]) e1 = e; }
        float w0 = p[e0], w1 = p[e1];
        float ws = w0 + w1;
        w0 /= ws; w1 /= ws;
        d_tope[t * 2 + 0] = e0; d_tope[t * 2 + 1] = e1;
        d_wgt[t * 2 + 0] = w0;  d_wgt[t * 2 + 1] = w1;
        atomicAdd(&d_count[e0], 1);
        atomicAdd(&d_count[e1], 1);
    }
}

__global__ void offsets_kernel() {
    if (threadIdx.x == 0) {
        int acc = 0;
        #pragma unroll
        for (int e = 0; e < NE; e++) {
            d_offset[e] = acc;
            acc += (d_count[e] + 127) & ~127;   // pad to 128 -> guard-free GEMMs
        }
    }
}

__global__ void assign_kernel() {
    int t = blockIdx.x * blockDim.x + threadIdx.x;
    if (t >= TT) return;
    #pragma unroll
    for (int k = 0; k < KSEL; k++) {
        int e = d_tope[t * 2 + k];
        int pos = atomicAdd(&d_fill[e], 1);
        int s = d_offset[e] + pos;
        d_rows[s] = t;
        d_slot[t * 2 + k] = s;
    }
}

// gather x into A-fragment-major fp16, slot order (padding slots read token 0)
__global__ void gather_x_kernel(const float* __restrict__ x) {
    int idx  = blockIdx.x * 256 + threadIdx.x;    // over SBLK*KB1*32
    if (idx >= SBLK * KB1 * 32) return;
    int lane = idx & 31;
    int kb   = (idx >> 5) % KB1;
    int sb   = (idx >> 5) / KB1;
    int gid = lane >> 2, tig = lane & 3;
    int t0 = d_rows[sb * 16 + gid];
    int t1 = d_rows[sb * 16 + gid + 8];
    int c  = kb * 16 + 2 * tig;
    float2 v00 = *reinterpret_cast<const float2*>(x + (size_t)t0 * HD + c);
    float2 v10 = *reinterpret_cast<const float2*>(x + (size_t)t1 * HD + c);
    float2 v01 = *reinterpret_cast<const float2*>(x + (size_t)t0 * HD + c + 8);
    float2 v11 = *reinterpret_cast<const float2*>(x + (size_t)t1 * HD + c + 8);
    uint4 o;
    o.x = h2u(v00.x, v00.y);   // a0: row gid,   k..k+1
    o.y = h2u(v10.x, v10.y);   // a1: row gid+8
    o.z = h2u(v01.x, v01.y);   // a2: row gid,   k+8..k+9
    o.w = h2u(v11.x, v11.y);   // a3: row gid+8
    d_xh[(size_t)idx] = o;
}

// =================== GEMM1: fp16 m16n8k16, fused SiLU·mul =================
// Block 128(M) x 64(N), BK=64 (4 k16/stage), 3-stage cp.async, 256 thr.
// Warps 4x2 (wm,wn), warp tile 32x32. Guard-free (padded slots).
// Stage smem: A 16KB | B1 8KB | B3 8KB = 32KB
#define G1_STG  32768
#define G1_AOFF 0
#define G1_B1OFF 16384
#define G1_B3OFF 24576
#define G1_SMEM (3 * G1_STG)
#define G1_NST  (HD / 64)     // 16 stages

__device__ __forceinline__ void g1_load(uint32_t sb, int st, int ks0, int tid,
                                        int sblk0, int e, int nb0) {
    uint32_t ab = sb + (uint32_t)st * G1_STG;
    #pragma unroll
    for (int i = 0; i < 4; i++) {                 // A: 1024 chunks of 16B
        int c = tid + i * 256;
        int lane = c & 31, lkb = (c >> 5) & 3, lsb = c >> 7;
        CP16(ab + G1_AOFF + c * 16,
             (const char*)(d_xh + (size_t)(((sblk0 + lsb) * KB1 + ks0 + lkb) * 32 + lane)));
    }
    #pragma unroll
    for (int i = 0; i < 2; i++) {                 // B1: 512 chunks
        int c = tid + i * 256;
        int inner = c & 15, b = c >> 4;
        int lk = b & 3, ln = b >> 2;
        size_t gidx = (size_t)(((e * NB1 + nb0 + ln) * KB1 + ks0 + lk) * 32) + inner * 2;
        CP16(ab + G1_B1OFF + c * 16, (const char*)(d_w1h + gidx));
        CP16(ab + G1_B3OFF + c * 16, (const char*)(d_w3h + gidx));
    }
    CPCOMMIT();
}

__global__ void __launch_bounds__(256, 2)
gemm1_mma() {
    int e  = blockIdx.z;
    int nt = blockIdx.x;                   // 64-col tile
    int m0 = blockIdx.y * 128;
    int cnt  = d_count[e];
    int pcnt = (cnt + 127) & ~127;
    if (m0 >= pcnt) return;
    int base  = d_offset[e];
    int sblk0 = (base + m0) >> 4;
    int nb0   = nt * 8;

    extern __shared__ char smem[];
    uint32_t sb = smem_u32(smem);

    int tid = threadIdx.x;
    int wid = tid >> 5, lane = tid & 31;
    int wm = wid & 3, wn = wid >> 2;       // 4x2
    int gid = lane >> 2, tig = lane & 3;

    float acc1[2][4][4], acc3[2][4][4];
    #pragma unroll
    for (int i = 0; i < 2; i++)
        #pragma unroll
        for (int j = 0; j < 4; j++)
            #pragma unroll
            for (int k = 0; k < 4; k++) { acc1[i][j][k] = 0.f; acc3[i][j][k] = 0.f; }

    g1_load(sb, 0, 0, tid, sblk0, e, nb0);
    g1_load(sb, 1, 4, tid, sblk0, e, nb0);

    for (int s = 0; s < G1_NST; s++) {
        if (s + 1 < G1_NST) CPWAIT1(); else CPWAIT0();
        __syncthreads();
        if (s + 2 < G1_NST) g1_load(sb, (s + 2) % 3, (s + 2) * 4, tid, sblk0, e, nb0);

        const char* st = smem + (size_t)(s % 3) * G1_STG;
        #pragma unroll
        for (int kk = 0; kk < 4; kk++) {
            uint4 a[2];
            #pragma unroll
            for (int mf = 0; mf < 2; mf++)
                a[mf] = *reinterpret_cast<const uint4*>(
                    st + G1_AOFF + (size_t)((((wm * 2 + mf) * 4 + kk) * 32 + lane)) * 16);
            uint2 b1[4], b3[4];
            #pragma unroll
            for (int nf = 0; nf < 4; nf++) {
                size_t bo = (size_t)((((wn * 4 + nf) * 4 + kk) * 32 + lane)) * 8;
                b1[nf] = *reinterpret_cast<const uint2*>(st + G1_B1OFF + bo);
                b3[nf] = *reinterpret_cast<const uint2*>(st + G1_B3OFF + bo);
            }
            #pragma unroll
            for (int nf = 0; nf < 4; nf++)
                #pragma unroll
                for (int mf = 0; mf < 2; mf++) {
                    mma16(acc1[mf][nf], a[mf].x, a[mf].y, a[mf].z, a[mf].w, b1[nf].x, b1[nf].y);
                    mma16(acc3[mf][nf], a[mf].x, a[mf].y, a[mf].z, a[mf].w, b3[nf].x, b3[nf].y);
                }
        }
        __syncthreads();
    }

    // epilogue: SiLU(h1)*h3 -> fp16, stored directly as GEMM2 A-fragments
    #pragma unroll
    for (int mf = 0; mf < 2; mf++) {
        int sblk = sblk0 + wm * 2 + mf;
        #pragma unroll
        for (int p = 0; p < 2; p++) {
            int nf0 = 2 * p, nf1 = 2 * p + 1;
            int kblkg = nt * 4 + wn * 2 + p;
            uint4 o;
            o.x = h2u(silu_mul(acc1[mf][nf0][0], acc3[mf][nf0][0]),
                      silu_mul(acc1[mf][nf0][1], acc3[mf][nf0][1]));   // row gid
            o.y = h2u(silu_mul(acc1[mf][nf0][2], acc3[mf][nf0][2]),
                      silu_mul(acc1[mf][nf0][3], acc3[mf][nf0][3]));   // row gid+8
            o.z = h2u(silu_mul(acc1[mf][nf1][0], acc3[mf][nf1][0]),
                      silu_mul(acc1[mf][nf1][1], acc3[mf][nf1][1]));
            o.w = h2u(silu_mul(acc1[mf][nf1][2], acc3[mf][nf1][2]),
                      silu_mul(acc1[mf][nf1][3], acc3[mf][nf1][3]));
            d_ih[(size_t)((sblk * KB2 + kblkg) * 32 + lane)] = o;
        }
    }
}

// =================== GEMM2: fp16 m16n8k16 ================================
// Block 128(M) x 128(N), BK=64, 3-stage, 256 thr. Warps 2x4, warp tile 64x32.
// Stage smem: A 16KB | B 16KB = 32KB
#define G2_STG  32768
#define G2_AOFF 0
#define G2_BOFF 16384
#define G2_SMEM (3 * G2_STG)
#define G2_NST  (FD / 64)     // 64 stages

__device__ __forceinline__ void g2_load(uint32_t sb, int st, int ks0, int tid,
                                        int sblk0, int e, int nb0) {
    uint32_t ab = sb + (uint32_t)st * G2_STG;
    #pragma unroll
    for (int i = 0; i < 4; i++) {                 // A: 1024 chunks
        int c = tid + i * 256;
        int lane = c & 31, lkb = (c >> 5) & 3, lsb = c >> 7;
        CP16(ab + G2_AOFF + c * 16,
             (const char*)(d_ih + (size_t)(((sblk0 + lsb) * KB2 + ks0 + lkb) * 32 + lane)));
    }
    #pragma unroll
    for (int i = 0; i < 4; i++) {                 // B: 1024 chunks (16 nblk x 4 kblk)
        int c = tid + i * 256;
        int inner = c & 15, b = c >> 4;
        int lk = b & 3, ln = b >> 2;
        size_t gidx = (size_t)(((e * NB2 + nb0 + ln) * KB2 + ks0 + lk) * 32) + inner * 2;
        CP16(ab + G2_BOFF + c * 16, (const char*)(d_w2h + gidx));
    }
    CPCOMMIT();
}

__global__ void __launch_bounds__(256, 2)
gemm2_mma() {
    int e  = blockIdx.z;
    int nt = blockIdx.x;                   // 128-col tile
    int m0 = blockIdx.y * 128;
    int cnt  = d_count[e];
    int pcnt = (cnt + 127) & ~127;
    if (m0 >= pcnt) return;
    int base  = d_offset[e];
    int sblk0 = (base + m0) >> 4;
    int nb0   = nt * 16;

    extern __shared__ char smem[];
    uint32_t sb = smem_u32(smem);

    int tid = threadIdx.x;
    int wid = tid >> 5, lane = tid & 31;
    int wm = wid & 1, wn = wid >> 1;       // 2x4
    int gid = lane >> 2, tig = lane & 3;

    float acc[4][4][4];
    #pragma unroll
    for (int i = 0; i < 4; i++)
        #pragma unroll
        for (int j = 0; j < 4; j++)
            #pragma unroll
            for (int k = 0; k < 4; k++) acc[i][j][k] = 0.f;

    g2_load(sb, 0, 0, tid, sblk0, e, nb0);
    g2_load(sb, 1, 4, tid, sblk0, e, nb0);

    for (int s = 0; s < G2_NST; s++) {
        if (s + 1 < G2_NST) CPWAIT1(); else CPWAIT0();
        __syncthreads();
        if (s + 2 < G2_NST) g2_load(sb, (s + 2) % 3, (s + 2) * 4, tid, sblk0, e, nb0);

        const char* st = smem + (size_t)(s % 3) * G2_STG;
        #pragma unroll
        for (int kk = 0; kk < 4; kk++) {
            uint4 a[4];
            #pragma unroll
            for (int mf = 0; mf < 4; mf++)
                a[mf] = *reinterpret_cast<const uint4*>(
                    st + G2_AOFF + (size_t)((((wm * 4 + mf) * 4 + kk) * 32 + lane)) * 16);
            uint2 b[4];
            #pragma unroll
            for (int nf = 0; nf < 4; nf++)
                b[nf] = *reinterpret_cast<const uint2*>(
                    st + G2_BOFF + (size_t)((((wn * 4 + nf) * 4 + kk) * 32 + lane)) * 8);
            #pragma unroll
            for (int nf = 0; nf < 4; nf++)
                #pragma unroll
                for (int mf = 0; mf < 4; mf++)
                    mma16(acc[mf][nf], a[mf].x, a[mf].y, a[mf].z, a[mf].w, b[nf].x, b[nf].y);
        }
        __syncthreads();
    }

    #pragma unroll
    for (int mf = 0; mf < 4; mf++) {
        int r = base + m0 + wm * 64 + mf * 16 + gid;
        #pragma unroll
        for (int nf = 0; nf < 4; nf++) {
            int n = nt * 128 + wn * 32 + nf * 8 + 2 * tig;
            *reinterpret_cast<float2*>(&d_y[(size_t)r * HD + n]) =
                make_float2(acc[mf][nf][0], acc[mf][nf][1]);
            *reinterpret_cast<float2*>(&d_y[(size_t)(r + 8) * HD + n]) =
                make_float2(acc[mf][nf][2], acc[mf][nf][3]);
        }
    }
}

// ---------------- combine ----------------
__global__ void combine_kernel(float* __restrict__ out) {
    int idx = blockIdx.x * blockDim.x + threadIdx.x;
    if (idx >= TT * (HD / 4)) return;
    int t  = idx / (HD / 4);
    int h4 = (idx % (HD / 4)) * 4;
    int s0 = d_slot[t * 2 + 0], s1 = d_slot[t * 2 + 1];
    float w0 = d_wgt[t * 2 + 0], w1 = d_wgt[t * 2 + 1];
    float4 y0 = *reinterpret_cast<const float4*>(&d_y[(size_t)s0 * HD + h4]);
    float4 y1 = *reinterpret_cast<const float4*>(&d_y[(size_t)s1 * HD + h4]);
    float4 o;
    o.x = w0 * y0.x + w1 * y1.x;
    o.y = w0 * y0.y + w1 * y1.y;
    o.z = w0 * y0.z + w1 * y1.z;
    o.w = w0 * y0.w + w1 * y1.w;
    *reinterpret_cast<float4*>(&out[(size_t)t * HD + h4]) = o;
}

// ---------------- launch ----------------
extern "C" void kernel_launch(void* const* d_in, const int* in_sizes, int n_in,
                              void* d_out, int out_size) {
    const float* x   = (const float*)d_in[0];  // [T, H]
    const float* gw  = (const float*)d_in[1];  // [E, H]
    const float* w1  = (const float*)d_in[2];  // [E, F, H]
    const float* w2  = (const float*)d_in[3];  // [E, H, F]
    const float* w3  = (const float*)d_in[4];  // [E, F, H]
    float* out       = (float*)d_out;          // [T*H] then logits [T*E]
    float* logits    = out + (size_t)TT * HD;

    cudaFuncSetAttribute(gemm1_mma, cudaFuncAttributeMaxDynamicSharedMemorySize, G1_SMEM);
    cudaFuncSetAttribute(gemm2_mma, cudaFuncAttributeMaxDynamicSharedMemorySize, G2_SMEM);

    uint2* w1h; cudaGetSymbolAddress((void**)&w1h, d_w1h);
    uint2* w3h; cudaGetSymbolAddress((void**)&w3h, d_w3h);
    uint2* w2h; cudaGetSymbolAddress((void**)&w2h, d_w2h);

    // prepass: compress+permute weights to fp16 fragment-major
    const int NWT = NE * NB1 * KB1 * 32;                     // 8.4M threads
    conv_w_kernel<<<NWT / 256, 256>>>(w1, w1h, NB1, KB1);
    conv_w_kernel<<<NWT / 256, 256>>>(w3, w3h, NB1, KB1);
    conv_w_kernel<<<(NE * NB2 * KB2 * 32) / 256, 256>>>(w2, w2h, NB2, KB2);

    // routing
    zero_counters_kernel<<<1, 32>>>();
    router_kernel<<<TT, 256>>>(x, gw, logits);
    offsets_kernel<<<1, 32>>>();
    zero_rows_kernel<<<(NSP + 255) / 256, 256>>>();
    assign_kernel<<<(TT + 255) / 256, 256>>>();
    gather_x_kernel<<<(SBLK * KB1 * 32 + 255) / 256, 256>>>(x);

    dim3 g1(FD / 64, TT / 128, NE);    // (64, 32, 8)
    gemm1_mma<<<g1, 256, G1_SMEM>>>();

    dim3 g2(HD / 128, TT / 128, NE);   // (8, 32, 8)
    gemm2_mma<<<g2, 256, G2_SMEM>>>();

    combine_kernel<<<(TT * (HD / 4) + 255) / 256, 256>>>(out);
}

// round 14
// speedup vs baseline: 2.7478x; 1.4926x over previous
#include <cuda_runtime.h>
#include <cuda_fp16.h>
#include <math.h>
#include <stdint.h>

// Problem constants (fixed by the dataset)
#define TT   4096
#define HD   1024
#define FD   4096
#define NE   8
#define KSEL 2
#define NSLOTS (TT * KSEL)
#define NSP   9216            // padded slots: 8192 + 8*128 headroom
#define SBLK  (NSP / 16)      // 576 slot blocks of 16
#define KB1   (HD / 16)       // 64  k16-blocks for GEMM1
#define NB1   (FD / 8)        // 512 n8-blocks  for GEMM1 weights
#define KB2   (FD / 16)       // 256 k16-blocks for GEMM2
#define NB2   (HD / 8)        // 128 n8-blocks  for GEMM2 weights

// ---------------- static scratch ----------------
__device__ int   d_count[NE];
__device__ int   d_fill[NE];
__device__ int   d_offset[NE];            // padded (multiple of 128) cumsum
__device__ int   d_rows[NSP];             // slot -> token (0 for padding)
__device__ float d_swgt[NSP];             // slot -> combine weight (0 for padding)
__device__ int   d_tope[TT * KSEL];
__device__ float d_tok_w[TT * KSEL];      // per-token top-k weights (router -> assign)
// fragment-major fp16 tensors (each uint4/uint2 = one lane's mma fragment)
__device__ __align__(16) uint4 d_xh [(size_t)SBLK * KB1 * 32];        // A frags G1
__device__ __align__(16) uint2 d_w1h[(size_t)NE * NB1 * KB1 * 32];    // B frags G1
__device__ __align__(16) uint2 d_w3h[(size_t)NE * NB1 * KB1 * 32];
__device__ __align__(16) uint4 d_ih [(size_t)SBLK * KB2 * 32];        // A frags G2 (inter)
__device__ __align__(16) uint2 d_w2h[(size_t)NE * NB2 * KB2 * 32];    // B frags G2

// ---------------- PTX helpers ----------------
__device__ __forceinline__ uint32_t smem_u32(const void* p) {
    uint32_t a;
    asm("{ .reg .u64 t; cvta.to.shared.u64 t, %1; cvt.u32.u64 %0, t; }" : "=r"(a) : "l"(p));
    return a;
}
#define CP16(s, g) \
    asm volatile("cp.async.cg.shared.global [%0], [%1], 16;" :: "r"(s), "l"(g) : "memory")
#define CPCOMMIT() asm volatile("cp.async.commit_group;" ::: "memory")
#define CPWAIT1()  asm volatile("cp.async.wait_group 1;" ::: "memory")
#define CPWAIT0()  asm volatile("cp.async.wait_group 0;" ::: "memory")

__device__ __forceinline__ uint32_t h2u(float a, float b) {
    __half2 h = __floats2half2_rn(a, b);
    return *reinterpret_cast<uint32_t*>(&h);
}

// D += A*B, m16n8k16 fp16 in / fp32 accum
__device__ __forceinline__ void mma16(float* c, uint32_t a0, uint32_t a1, uint32_t a2,
                                      uint32_t a3, uint32_t b0, uint32_t b1) {
    asm volatile(
        "mma.sync.aligned.m16n8k16.row.col.f32.f16.f16.f32 "
        "{%0,%1,%2,%3}, {%4,%5,%6,%7}, {%8,%9}, {%0,%1,%2,%3};"
        : "+f"(c[0]), "+f"(c[1]), "+f"(c[2]), "+f"(c[3])
        : "r"(a0), "r"(a1), "r"(a2), "r"(a3), "r"(b0), "r"(b1));
}

__device__ __forceinline__ float silu_mul(float v, float g) {
    return v / (1.f + __expf(-v)) * g;
}

// ---------------- prepass: fp32 weights -> fp16 fragment-major ----------------
__global__ void conv_w_kernel(const float* __restrict__ W, uint2* __restrict__ out,
                              int NBLK, int KBLK) {
    int idx  = blockIdx.x * 256 + threadIdx.x;       // over NE*NBLK*KBLK*32
    int lane = idx & 31;
    int rest = idx >> 5;
    int kb   = rest % KBLK;
    int nb   = (rest / KBLK) % NBLK;
    int e    = rest / (KBLK * NBLK);
    if (e >= NE) return;
    int gid = lane >> 2, tig = lane & 3;
    int K   = KBLK * 16;
    size_t row = (size_t)(e * NBLK + nb) * 8 + gid;
    int c   = kb * 16 + 2 * tig;
    float2 v0 = *reinterpret_cast<const float2*>(W + row * K + c);
    float2 v1 = *reinterpret_cast<const float2*>(W + row * K + c + 8);
    uint2 o;
    o.x = h2u(v0.x, v0.y);
    o.y = h2u(v1.x, v1.y);
    out[(size_t)idx] = o;
}

// ---------------- routing kernels ----------------
// merged zero: counters, slot->token map, slot->weight map
__global__ void zero_all_kernel() {
    int i = blockIdx.x * blockDim.x + threadIdx.x;
    if (i < NE) { d_count[i] = 0; d_fill[i] = 0; }
    if (i < NSP) { d_rows[i] = 0; d_swgt[i] = 0.f; }
}

// zero the output region scattered into by GEMM2's atomic epilogue
__global__ void zero_out_kernel(float4* __restrict__ out4) {
    int i = blockIdx.x * blockDim.x + threadIdx.x;
    if (i < TT * (HD / 4)) out4[i] = make_float4(0.f, 0.f, 0.f, 0.f);
}

__global__ void router_kernel(const float* __restrict__ x,
                              const float* __restrict__ gw,
                              float* __restrict__ logits_out) {
    int t    = blockIdx.x;
    int warp = threadIdx.x >> 5;
    int lane = threadIdx.x & 31;
    const float* xr = x + (size_t)t * HD;
    const float* gr = gw + (size_t)warp * HD;
    float s = 0.f;
    #pragma unroll 8
    for (int i = lane; i < HD; i += 32) s += xr[i] * gr[i];
    #pragma unroll
    for (int o = 16; o; o >>= 1) s += __shfl_xor_sync(0xffffffffu, s, o);
    __shared__ float sl[NE];
    if (lane == 0) sl[warp] = s;
    __syncthreads();
    if (threadIdx.x < NE) logits_out[(size_t)t * NE + threadIdx.x] = sl[threadIdx.x];
    if (threadIdx.x == 0) {
        float mx = sl[0];
        #pragma unroll
        for (int e = 1; e < NE; e++) mx = fmaxf(mx, sl[e]);
        float p[NE];
        #pragma unroll
        for (int e = 0; e < NE; e++) p[e] = expf(sl[e] - mx);
        int e0 = 0;
        #pragma unroll
        for (int e = 1; e < NE; e++) if (p[e] > p[e0]) e0 = e;
        int e1 = (e0 == 0) ? 1 : 0;
        #pragma unroll
        for (int e = 0; e < NE; e++) { if (e == e0) continue; if (p[e] > p[e1]) e1 = e; }
        float w0 = p[e0], w1 = p[e1];
        float ws = w0 + w1;
        w0 /= ws; w1 /= ws;
        d_tope[t * 2 + 0] = e0; d_tope[t * 2 + 1] = e1;
        d_tok_w[t * 2 + 0] = w0;
        d_tok_w[t * 2 + 1] = w1;
        atomicAdd(&d_count[e0], 1);
        atomicAdd(&d_count[e1], 1);
    }
}

__global__ void offsets_kernel() {
    if (threadIdx.x == 0) {
        int acc = 0;
        #pragma unroll
        for (int e = 0; e < NE; e++) {
            d_offset[e] = acc;
            acc += (d_count[e] + 127) & ~127;   // pad to 128 -> guard-free GEMMs
        }
    }
}

__global__ void assign_kernel() {
    int t = blockIdx.x * blockDim.x + threadIdx.x;
    if (t >= TT) return;
    #pragma unroll
    for (int k = 0; k < KSEL; k++) {
        int e = d_tope[t * 2 + k];
        int pos = atomicAdd(&d_fill[e], 1);
        int s = d_offset[e] + pos;
        d_rows[s] = t;
        d_swgt[s] = d_tok_w[t * 2 + k];
    }
}

// gather x into A-fragment-major fp16, slot order (padding slots read token 0)
__global__ void gather_x_kernel(const float* __restrict__ x) {
    int idx  = blockIdx.x * 256 + threadIdx.x;    // over SBLK*KB1*32
    if (idx >= SBLK * KB1 * 32) return;
    int lane = idx & 31;
    int kb   = (idx >> 5) % KB1;
    int sb   = (idx >> 5) / KB1;
    int gid = lane >> 2, tig = lane & 3;
    int t0 = d_rows[sb * 16 + gid];
    int t1 = d_rows[sb * 16 + gid + 8];
    int c  = kb * 16 + 2 * tig;
    float2 v00 = *reinterpret_cast<const float2*>(x + (size_t)t0 * HD + c);
    float2 v10 = *reinterpret_cast<const float2*>(x + (size_t)t1 * HD + c);
    float2 v01 = *reinterpret_cast<const float2*>(x + (size_t)t0 * HD + c + 8);
    float2 v11 = *reinterpret_cast<const float2*>(x + (size_t)t1 * HD + c + 8);
    uint4 o;
    o.x = h2u(v00.x, v00.y);
    o.y = h2u(v10.x, v10.y);
    o.z = h2u(v01.x, v01.y);
    o.w = h2u(v11.x, v11.y);
    d_xh[(size_t)idx] = o;
}

// =================== GEMM1: fp16 m16n8k16, fused SiLU·mul =================
// Block 128(M) x 64(N), BK=64, 3-stage cp.async, 256 thr, warps 4x2.
// blockIdx.x = M-TILE (fastest) -> concurrent wave shares weight slices in L2.
#define G1_STG  32768
#define G1_AOFF 0
#define G1_B1OFF 16384
#define G1_B3OFF 24576
#define G1_SMEM (3 * G1_STG)
#define G1_NST  (HD / 64)     // 16 stages

__device__ __forceinline__ void g1_load(uint32_t sb, int st, int ks0, int tid,
                                        int sblk0, int e, int nb0) {
    uint32_t ab = sb + (uint32_t)st * G1_STG;
    #pragma unroll
    for (int i = 0; i < 4; i++) {                 // A: 1024 chunks of 16B
        int c = tid + i * 256;
        int lane = c & 31, lkb = (c >> 5) & 3, lsb = c >> 7;
        CP16(ab + G1_AOFF + c * 16,
             (const char*)(d_xh + (size_t)(((sblk0 + lsb) * KB1 + ks0 + lkb) * 32 + lane)));
    }
    #pragma unroll
    for (int i = 0; i < 2; i++) {                 // B1/B3: 512 chunks each
        int c = tid + i * 256;
        int inner = c & 15, b = c >> 4;
        int lk = b & 3, ln = b >> 2;
        size_t gidx = (size_t)(((e * NB1 + nb0 + ln) * KB1 + ks0 + lk) * 32) + inner * 2;
        CP16(ab + G1_B1OFF + c * 16, (const char*)(d_w1h + gidx));
        CP16(ab + G1_B3OFF + c * 16, (const char*)(d_w3h + gidx));
    }
    CPCOMMIT();
}

__global__ void __launch_bounds__(256, 2)
gemm1_mma() {
    int e  = blockIdx.z;
    int nt = blockIdx.y;                   // 64-col tile (slow axis)
    int m0 = blockIdx.x * 128;             // M-tile fastest -> L2 weight reuse
    int cnt  = d_count[e];
    int pcnt = (cnt + 127) & ~127;
    if (m0 >= pcnt) return;
    int base  = d_offset[e];
    int sblk0 = (base + m0) >> 4;
    int nb0   = nt * 8;

    extern __shared__ char smem[];
    uint32_t sb = smem_u32(smem);

    int tid = threadIdx.x;
    int wid = tid >> 5, lane = tid & 31;
    int wm = wid & 3, wn = wid >> 2;       // 4x2
    int gid = lane >> 2, tig = lane & 3;

    float acc1[2][4][4], acc3[2][4][4];
    #pragma unroll
    for (int i = 0; i < 2; i++)
        #pragma unroll
        for (int j = 0; j < 4; j++)
            #pragma unroll
            for (int k = 0; k < 4; k++) { acc1[i][j][k] = 0.f; acc3[i][j][k] = 0.f; }

    g1_load(sb, 0, 0, tid, sblk0, e, nb0);
    g1_load(sb, 1, 4, tid, sblk0, e, nb0);

    for (int s = 0; s < G1_NST; s++) {
        if (s + 1 < G1_NST) CPWAIT1(); else CPWAIT0();
        __syncthreads();
        if (s + 2 < G1_NST) g1_load(sb, (s + 2) % 3, (s + 2) * 4, tid, sblk0, e, nb0);

        const char* st = smem + (size_t)(s % 3) * G1_STG;
        #pragma unroll
        for (int kk = 0; kk < 4; kk++) {
            uint4 a[2];
            #pragma unroll
            for (int mf = 0; mf < 2; mf++)
                a[mf] = *reinterpret_cast<const uint4*>(
                    st + G1_AOFF + (size_t)((((wm * 2 + mf) * 4 + kk) * 32 + lane)) * 16);
            uint2 b1[4], b3[4];
            #pragma unroll
            for (int nf = 0; nf < 4; nf++) {
                size_t bo = (size_t)((((wn * 4 + nf) * 4 + kk) * 32 + lane)) * 8;
                b1[nf] = *reinterpret_cast<const uint2*>(st + G1_B1OFF + bo);
                b3[nf] = *reinterpret_cast<const uint2*>(st + G1_B3OFF + bo);
            }
            #pragma unroll
            for (int nf = 0; nf < 4; nf++)
                #pragma unroll
                for (int mf = 0; mf < 2; mf++) {
                    mma16(acc1[mf][nf], a[mf].x, a[mf].y, a[mf].z, a[mf].w, b1[nf].x, b1[nf].y);
                    mma16(acc3[mf][nf], a[mf].x, a[mf].y, a[mf].z, a[mf].w, b3[nf].x, b3[nf].y);
                }
        }
        __syncthreads();
    }

    // epilogue: SiLU(h1)*h3 -> fp16, stored directly as GEMM2 A-fragments
    #pragma unroll
    for (int mf = 0; mf < 2; mf++) {
        int sblk = sblk0 + wm * 2 + mf;
        #pragma unroll
        for (int p = 0; p < 2; p++) {
            int nf0 = 2 * p, nf1 = 2 * p + 1;
            int kblkg = nt * 4 + wn * 2 + p;
            uint4 o;
            o.x = h2u(silu_mul(acc1[mf][nf0][0], acc3[mf][nf0][0]),
                      silu_mul(acc1[mf][nf0][1], acc3[mf][nf0][1]));
            o.y = h2u(silu_mul(acc1[mf][nf0][2], acc3[mf][nf0][2]),
                      silu_mul(acc1[mf][nf0][3], acc3[mf][nf0][3]));
            o.z = h2u(silu_mul(acc1[mf][nf1][0], acc3[mf][nf1][0]),
                      silu_mul(acc1[mf][nf1][1], acc3[mf][nf1][1]));
            o.w = h2u(silu_mul(acc1[mf][nf1][2], acc3[mf][nf1][2]),
                      silu_mul(acc1[mf][nf1][3], acc3[mf][nf1][3]));
            d_ih[(size_t)((sblk * KB2 + kblkg) * 32 + lane)] = o;
        }
    }
}

// =================== GEMM2: fp16 m16n8k16, fused weighted scatter ==========
// Block 128(M) x 128(N), BK=64, 3-stage, 256 thr, warps 2x4.
// blockIdx.x = M-TILE (fastest). Epilogue: out[token] += w_slot * acc (atomic;
// exactly 2 nonzero contributions per element -> commutative -> deterministic).
#define G2_STG  32768
#define G2_AOFF 0
#define G2_BOFF 16384
#define G2_SMEM (3 * G2_STG)
#define G2_NST  (FD / 64)     // 64 stages

__device__ __forceinline__ void g2_load(uint32_t sb, int st, int ks0, int tid,
                                        int sblk0, int e, int nb0) {
    uint32_t ab = sb + (uint32_t)st * G2_STG;
    #pragma unroll
    for (int i = 0; i < 4; i++) {                 // A: 1024 chunks
        int c = tid + i * 256;
        int lane = c & 31, lkb = (c >> 5) & 3, lsb = c >> 7;
        CP16(ab + G2_AOFF + c * 16,
             (const char*)(d_ih + (size_t)(((sblk0 + lsb) * KB2 + ks0 + lkb) * 32 + lane)));
    }
    #pragma unroll
    for (int i = 0; i < 4; i++) {                 // B: 1024 chunks
        int c = tid + i * 256;
        int inner = c & 15, b = c >> 4;
        int lk = b & 3, ln = b >> 2;
        size_t gidx = (size_t)(((e * NB2 + nb0 + ln) * KB2 + ks0 + lk) * 32) + inner * 2;
        CP16(ab + G2_BOFF + c * 16, (const char*)(d_w2h + gidx));
    }
    CPCOMMIT();
}

__global__ void __launch_bounds__(256, 2)
gemm2_mma(float* __restrict__ out) {
    int e  = blockIdx.z;
    int nt = blockIdx.y;                   // 128-col tile (slow)
    int m0 = blockIdx.x * 128;             // M-tile fastest
    int cnt  = d_count[e];
    int pcnt = (cnt + 127) & ~127;
    if (m0 >= pcnt) return;
    int base  = d_offset[e];
    int sblk0 = (base + m0) >> 4;
    int nb0   = nt * 16;

    extern __shared__ char smem[];
    uint32_t sb = smem_u32(smem);

    int tid = threadIdx.x;
    int wid = tid >> 5, lane = tid & 31;
    int wm = wid & 1, wn = wid >> 1;       // 2x4
    int gid = lane >> 2, tig = lane & 3;

    float acc[4][4][4];
    #pragma unroll
    for (int i = 0; i < 4; i++)
        #pragma unroll
        for (int j = 0; j < 4; j++)
            #pragma unroll
            for (int k = 0; k < 4; k++) acc[i][j][k] = 0.f;

    g2_load(sb, 0, 0, tid, sblk0, e, nb0);
    g2_load(sb, 1, 4, tid, sblk0, e, nb0);

    for (int s = 0; s < G2_NST; s++) {
        if (s + 1 < G2_NST) CPWAIT1(); else CPWAIT0();
        __syncthreads();
        if (s + 2 < G2_NST) g2_load(sb, (s + 2) % 3, (s + 2) * 4, tid, sblk0, e, nb0);

        const char* st = smem + (size_t)(s % 3) * G2_STG;
        #pragma unroll
        for (int kk = 0; kk < 4; kk++) {
            uint4 a[4];
            #pragma unroll
            for (int mf = 0; mf < 4; mf++)
                a[mf] = *reinterpret_cast<const uint4*>(
                    st + G2_AOFF + (size_t)((((wm * 4 + mf) * 4 + kk) * 32 + lane)) * 16);
            uint2 b[4];
            #pragma unroll
            for (int nf = 0; nf < 4; nf++)
                b[nf] = *reinterpret_cast<const uint2*>(
                    st + G2_BOFF + (size_t)((((wn * 4 + nf) * 4 + kk) * 32 + lane)) * 8);
            #pragma unroll
            for (int nf = 0; nf < 4; nf++)
                #pragma unroll
                for (int mf = 0; mf < 4; mf++)
                    mma16(acc[mf][nf], a[mf].x, a[mf].y, a[mf].z, a[mf].w, b[nf].x, b[nf].y);
        }
        __syncthreads();
    }

    // fused combine: weighted atomic scatter to out[token]
    #pragma unroll
    for (int mf = 0; mf < 4; mf++) {
        int r  = base + m0 + wm * 64 + mf * 16 + gid;
        int t0 = d_rows[r],     t1 = d_rows[r + 8];
        float w0 = d_swgt[r],   w1 = d_swgt[r + 8];
        #pragma unroll
        for (int nf = 0; nf < 4; nf++) {
            int n = nt * 128 + wn * 32 + nf * 8 + 2 * tig;
            if (w0 != 0.f) {
                atomicAdd(&out[(size_t)t0 * HD + n],     w0 * acc[mf][nf][0]);
                atomicAdd(&out[(size_t)t0 * HD + n + 1], w0 * acc[mf][nf][1]);
            }
            if (w1 != 0.f) {
                atomicAdd(&out[(size_t)t1 * HD + n],     w1 * acc[mf][nf][2]);
                atomicAdd(&out[(size_t)t1 * HD + n + 1], w1 * acc[mf][nf][3]);
            }
        }
    }
}

// ---------------- launch ----------------
extern "C" void kernel_launch(void* const* d_in, const int* in_sizes, int n_in,
                              void* d_out, int out_size) {
    const float* x   = (const float*)d_in[0];  // [T, H]
    const float* gw  = (const float*)d_in[1];  // [E, H]
    const float* w1  = (const float*)d_in[2];  // [E, F, H]
    const float* w2  = (const float*)d_in[3];  // [E, H, F]
    const float* w3  = (const float*)d_in[4];  // [E, F, H]
    float* out       = (float*)d_out;          // [T*H] then logits [T*E]
    float* logits    = out + (size_t)TT * HD;

    cudaFuncSetAttribute(gemm1_mma, cudaFuncAttributeMaxDynamicSharedMemorySize, G1_SMEM);
    cudaFuncSetAttribute(gemm2_mma, cudaFuncAttributeMaxDynamicSharedMemorySize, G2_SMEM);

    uint2* w1h; cudaGetSymbolAddress((void**)&w1h, d_w1h);
    uint2* w3h; cudaGetSymbolAddress((void**)&w3h, d_w3h);
    uint2* w2h; cudaGetSymbolAddress((void**)&w2h, d_w2h);

    // prepass: compress+permute weights to fp16 fragment-major
    const int NWT = NE * NB1 * KB1 * 32;
    conv_w_kernel<<<NWT / 256, 256>>>(w1, w1h, NB1, KB1);
    conv_w_kernel<<<NWT / 256, 256>>>(w3, w3h, NB1, KB1);
    conv_w_kernel<<<(NE * NB2 * KB2 * 32) / 256, 256>>>(w2, w2h, NB2, KB2);

    // routing + output zero
    zero_all_kernel<<<(NSP + 255) / 256, 256>>>();
    zero_out_kernel<<<(TT * (HD / 4) + 255) / 256, 256>>>((float4*)out);
    router_kernel<<<TT, 256>>>(x, gw, logits);
    offsets_kernel<<<1, 32>>>();
    assign_kernel<<<(TT + 255) / 256, 256>>>();
    gather_x_kernel<<<(SBLK * KB1 * 32 + 255) / 256, 256>>>(x);

    dim3 g1(TT / 128, FD / 64, NE);    // (32 m, 64 n, 8 e) — m fastest
    gemm1_mma<<<g1, 256, G1_SMEM>>>();

    dim3 g2(TT / 128, HD / 128, NE);   // (32 m, 8 n, 8 e) — m fastest
    gemm2_mma<<<g2, 256, G2_SMEM>>>(out);
}